// round 1
// baseline (speedup 1.0000x reference)
#include <cuda_runtime.h>
#include <math.h>

#define N_NODES 100000
#define N_EDGES 1000000

// ---------------- scratch (static device globals; no allocation) ----------------
__device__ float g_H[(size_t)N_NODES * 128];     // [N][128] : x@W0 | x@W1
__device__ float g_AGG[(size_t)N_NODES * 128];   // [N][128] : A h0  | A h1
__device__ float g_AGG2[(size_t)N_NODES * 64];   // [N][64]  : A (A h1)
__device__ float g_deg1[N_NODES];                // A 1 (edge_attr weighted)
__device__ float g_deg2[N_NODES];                // A deg1

// ---------------- zero accumulators (needed every launch/replay) ----------------
__global__ void zero_kernel() {
    const size_t stride = (size_t)gridDim.x * blockDim.x;
    size_t t = (size_t)blockIdx.x * blockDim.x + threadIdx.x;
    float4 z = make_float4(0.f, 0.f, 0.f, 0.f);
    float4* a = (float4*)g_AGG;
    for (size_t i = t; i < (size_t)N_NODES * 32; i += stride) a[i] = z;
    float4* a2 = (float4*)g_AGG2;
    for (size_t i = t; i < (size_t)N_NODES * 16; i += stride) a2[i] = z;
    float4* d1 = (float4*)g_deg1;
    for (size_t i = t; i < N_NODES / 4; i += stride) d1[i] = z;
    float4* d2 = (float4*)g_deg2;
    for (size_t i = t; i < N_NODES / 4; i += stride) d2[i] = z;
}

// ---------------- GEMM: H[:,0:64] = x@W0, H[:,64:128] = x@W1 ----------------
// block: 256 threads, tile 128 rows x 64 cols, blockIdx.y selects W0/W1.
// per thread: 8 rows x 4 cols register tile. K chunked by 16 through smem.
__global__ __launch_bounds__(256) void gemm_kernel(const float* __restrict__ x,
                                                   const float* __restrict__ W0,
                                                   const float* __restrict__ W1) {
    __shared__ float Ws[128 * 64];      // 32 KB
    __shared__ float Xs[128 * 17];      // 8.5 KB, padded stride 17

    const float* W = (blockIdx.y == 0) ? W0 : W1;
    const int tid = threadIdx.x;
    for (int i = tid; i < 128 * 64; i += 256) Ws[i] = W[i];

    const int r0 = blockIdx.x * 128;
    const int tx = tid & 15;        // col group (4 cols)
    const int ty = tid >> 4;        // row group (8 rows)

    float acc[8][4];
#pragma unroll
    for (int i = 0; i < 8; i++)
#pragma unroll
        for (int j = 0; j < 4; j++) acc[i][j] = 0.f;

    for (int kk = 0; kk < 128; kk += 16) {
        __syncthreads();
        // load 128 rows x 16 k into Xs
#pragma unroll
        for (int i = 0; i < 8; i++) {
            int idx = tid + i * 256;
            int rr = idx >> 4;
            int k = idx & 15;
            int row = r0 + rr;
            Xs[rr * 17 + k] = (row < N_NODES) ? x[(size_t)row * 128 + kk + k] : 0.f;
        }
        __syncthreads();
#pragma unroll
        for (int k = 0; k < 16; k++) {
            float4 b = *(const float4*)&Ws[(kk + k) * 64 + tx * 4];
#pragma unroll
            for (int ri = 0; ri < 8; ri++) {
                float a = Xs[(ty * 8 + ri) * 17 + k];
                acc[ri][0] += a * b.x;
                acc[ri][1] += a * b.y;
                acc[ri][2] += a * b.z;
                acc[ri][3] += a * b.w;
            }
        }
    }

    const int cbase = blockIdx.y * 64 + tx * 4;
#pragma unroll
    for (int ri = 0; ri < 8; ri++) {
        int row = r0 + ty * 8 + ri;
        if (row < N_NODES) {
            *(float4*)&g_H[(size_t)row * 128 + cbase] =
                make_float4(acc[ri][0], acc[ri][1], acc[ri][2], acc[ri][3]);
        }
    }
}

// vector reduction into global memory
__device__ __forceinline__ void red_v4(float* dst, float4 p) {
    asm volatile(
        "{\n\t"
        ".reg .u64 p64;\n\t"
        "cvta.to.global.u64 p64, %0;\n\t"
        "red.global.add.v4.f32 [p64], {%1, %2, %3, %4};\n\t"
        "}"
        :: "l"(dst), "f"(p.x), "f"(p.y), "f"(p.z), "f"(p.w)
        : "memory");
}

// ---------------- pass 1: AGG = A [h0|h1], deg1 = A 1  (warp per edge) ----------------
__global__ __launch_bounds__(256) void spmm1_kernel(const int* __restrict__ ei,
                                                    const float* __restrict__ ea) {
    const int w = (blockIdx.x * 256 + threadIdx.x) >> 5;
    const int lane = threadIdx.x & 31;
    if (w >= N_EDGES) return;
    const int r = __ldg(&ei[w]);
    const int c = __ldg(&ei[N_EDGES + w]);
    const float v = __ldg(&ea[w]);

    float4 h = ((const float4*)g_H)[(size_t)c * 32 + lane];
    float4 p = make_float4(h.x * v, h.y * v, h.z * v, h.w * v);
    red_v4(g_AGG + (size_t)r * 128 + lane * 4, p);
    if (lane == 0) atomicAdd(&g_deg1[r], v);
}

// ---------------- pass 2: AGG2 = A (A h1), deg2 = A deg1  (half-warp per edge) ------
__global__ __launch_bounds__(256) void spmm2_kernel(const int* __restrict__ ei,
                                                    const float* __restrict__ ea) {
    const int t = blockIdx.x * 256 + threadIdx.x;
    const int e = t >> 4;
    const int l = t & 15;
    if (e >= N_EDGES) return;
    const int r = __ldg(&ei[e]);
    const int c = __ldg(&ei[N_EDGES + e]);
    const float v = __ldg(&ea[e]);

    // gather cols 64..127 of AGG row c  (= (A h1)[c])
    float4 tv = ((const float4*)g_AGG)[(size_t)c * 32 + 16 + l];
    float4 p = make_float4(tv.x * v, tv.y * v, tv.z * v, tv.w * v);
    red_v4(g_AGG2 + (size_t)r * 64 + l * 4, p);
    if (l == 0) atomicAdd(&g_deg2[r], v * g_deg1[c]);
}

// ---------------- epilogue: normalize + bias + adaptive encoder (warp per row) ------
__global__ __launch_bounds__(256) void epi_kernel(int hop,
                                                  const float* __restrict__ b,
                                                  const float* __restrict__ fc,
                                                  const float* __restrict__ bf,
                                                  float* __restrict__ out) {
    const int w = (blockIdx.x * 256 + threadIdx.x) >> 5;
    const int lane = threadIdx.x & 31;
    if (w >= N_NODES) return;

    const float* agg = (hop == 0) ? g_AGG : g_AGG2;
    const int stride = (hop == 0) ? 128 : 64;
    const float d = (hop == 0) ? g_deg1[w] : g_deg2[w];

    float2 acc = *(const float2*)&agg[(size_t)w * stride + 2 * lane];
    float2 y;
    if (d > 0.f) {
        float inv = 1.f / d;
        y.x = acc.x * inv;
        y.y = acc.y * inv;
    } else {
        y.x = 0.f;
        y.y = 0.f;
    }
    y.x += __ldg(&b[2 * lane]);
    y.y += __ldg(&b[2 * lane + 1]);

    float dot = y.x * __ldg(&fc[2 * lane]) + y.y * __ldg(&fc[2 * lane + 1]);
#pragma unroll
    for (int s = 16; s; s >>= 1) dot += __shfl_xor_sync(0xffffffffu, dot, s);
    float g = 1.f / (1.f + expf(-(dot + __ldg(&bf[0]))));

    float2 o;
    o.x = (y.x > 0.f) ? y.x : g * y.x;
    o.y = (y.y > 0.f) ? y.y : g * y.y;
    *(float2*)&out[(size_t)w * 128 + hop * 64 + 2 * lane] = o;
}

// ---------------- launch ----------------
extern "C" void kernel_launch(void* const* d_in, const int* in_sizes, int n_in,
                              void* d_out, int out_size) {
    const float* x   = (const float*)d_in[0];
    const int*   ei  = (const int*)d_in[1];
    const float* ea  = (const float*)d_in[2];
    const float* W0  = (const float*)d_in[3];
    const float* b0  = (const float*)d_in[4];
    const float* W1  = (const float*)d_in[5];
    const float* b1  = (const float*)d_in[6];
    const float* fc0 = (const float*)d_in[7];
    const float* bf0 = (const float*)d_in[8];
    const float* fc1 = (const float*)d_in[9];
    const float* bf1 = (const float*)d_in[10];
    float* out = (float*)d_out;

    zero_kernel<<<2048, 256>>>();

    dim3 ggrid((N_NODES + 127) / 128, 2);
    gemm_kernel<<<ggrid, 256>>>(x, W0, W1);

    spmm1_kernel<<<(N_EDGES * 32 + 255) / 256, 256>>>(ei, ea);   // 125000 blocks
    spmm2_kernel<<<(N_EDGES * 16 + 255) / 256, 256>>>(ei, ea);   // 62500 blocks

    epi_kernel<<<(N_NODES * 32 + 255) / 256, 256>>>(0, b0, fc0, bf0, out);
    epi_kernel<<<(N_NODES * 32 + 255) / 256, 256>>>(1, b1, fc1, bf1, out);
}

// round 2
// speedup vs baseline: 1.3109x; 1.3109x over previous
#include <cuda_runtime.h>
#include <math.h>

#define N_NODES 100000
#define N_EDGES 1000000

// ---------------- scratch (static device globals; no allocation) ----------------
__device__ float g_H[(size_t)N_NODES * 128];     // [N][128] : x@W0 | x@W1
__device__ float g_AGG[(size_t)N_NODES * 128];   // [N][128] : A h0  | A h1
__device__ float g_AGG2[(size_t)N_NODES * 64];   // [N][64]  : A (A h1)
__device__ float g_deg1[N_NODES];                // A 1
__device__ float g_deg2[N_NODES];                // A deg1

// ---------------- zero accumulators ----------------
__global__ void zero_kernel() {
    const size_t stride = (size_t)gridDim.x * blockDim.x;
    size_t t = (size_t)blockIdx.x * blockDim.x + threadIdx.x;
    float4 z = make_float4(0.f, 0.f, 0.f, 0.f);
    float4* a = (float4*)g_AGG;
    for (size_t i = t; i < (size_t)N_NODES * 32; i += stride) a[i] = z;
    float4* a2 = (float4*)g_AGG2;
    for (size_t i = t; i < (size_t)N_NODES * 16; i += stride) a2[i] = z;
    float4* d1 = (float4*)g_deg1;
    for (size_t i = t; i < N_NODES / 4; i += stride) d1[i] = z;
    float4* d2 = (float4*)g_deg2;
    for (size_t i = t; i < N_NODES / 4; i += stride) d2[i] = z;
}

// ---------------- packed f32x2 helpers ----------------
__device__ __forceinline__ unsigned long long pack2(float a, float b) {
    unsigned long long r;
    asm("mov.b64 %0, {%1, %2};" : "=l"(r) : "f"(a), "f"(b));
    return r;
}
__device__ __forceinline__ void ffma2(unsigned long long& d, unsigned long long a,
                                      unsigned long long b) {
    asm("fma.rn.f32x2 %0, %1, %2, %0;" : "+l"(d) : "l"(a), "l"(b));
}
__device__ __forceinline__ float2 unpack2(unsigned long long v) {
    float2 f;
    asm("mov.b64 {%0, %1}, %2;" : "=f"(f.x), "=f"(f.y) : "l"(v));
    return f;
}

// ---------------- GEMM: H[:,0:64] = x@W0, H[:,64:128] = x@W1 ----------------
// 256 threads, tile 128 rows x 64 cols, blockIdx.y selects W0/W1.
// Per thread: 4 row-PAIRS x 4 cols of f32x2 accumulators (8 rows x 4 cols).
// A is staged in shared as u64 row-pairs so FFMA2 operands need no repacking.
__global__ __launch_bounds__(256) void gemm_kernel(const float* __restrict__ x,
                                                   const float* __restrict__ W0,
                                                   const float* __restrict__ W1) {
    __shared__ float Ws[128 * 64];                       // 32 KB
    __shared__ unsigned long long Xs2[64 * 17];          // 8.5 KB: [rowpair][k]

    const float* W = blockIdx.y ? W1 : W0;
    const int tid = threadIdx.x;
    for (int i = tid; i < 128 * 64 / 4; i += 256)
        ((float4*)Ws)[i] = ((const float4*)W)[i];

    const int r0 = blockIdx.x * 128;
    const int tx = tid & 15;   // col group (4 cols)
    const int ty = tid >> 4;   // row group (8 rows = 4 pairs)

    unsigned long long acc[4][4];
#pragma unroll
    for (int p = 0; p < 4; p++)
#pragma unroll
        for (int c = 0; c < 4; c++) acc[p][c] = 0ull;

    float* Xf = (float*)Xs2;   // float view: pair p, k -> (p*17+k)*2 + (row&1)

    for (int kk = 0; kk < 128; kk += 16) {
        __syncthreads();
        // load 128 rows x 16 k into Xs2 (row-pair packed)
#pragma unroll
        for (int i = 0; i < 2; i++) {
            int idx = tid + i * 256;          // 0..511 : 512 float4 = 128 rows * 4
            int rr = idx >> 2;                // row within tile
            int kq = idx & 3;                 // which float4 of the 16-k chunk
            int row = r0 + rr;
            float4 v = (row < N_NODES)
                           ? *(const float4*)&x[(size_t)row * 128 + kk + kq * 4]
                           : make_float4(0.f, 0.f, 0.f, 0.f);
            int p = rr >> 1, half = rr & 1;
            float* dst = &Xf[((p * 17) + kq * 4) * 2 + half];
            dst[0] = v.x; dst[2] = v.y; dst[4] = v.z; dst[6] = v.w;
        }
        __syncthreads();
#pragma unroll
        for (int k = 0; k < 16; k++) {
            float4 b = *(const float4*)&Ws[(kk + k) * 64 + tx * 4];
            unsigned long long bb[4];
            bb[0] = pack2(b.x, b.x);
            bb[1] = pack2(b.y, b.y);
            bb[2] = pack2(b.z, b.z);
            bb[3] = pack2(b.w, b.w);
#pragma unroll
            for (int p = 0; p < 4; p++) {
                unsigned long long aa = Xs2[(ty * 4 + p) * 17 + k];
                ffma2(acc[p][0], aa, bb[0]);
                ffma2(acc[p][1], aa, bb[1]);
                ffma2(acc[p][2], aa, bb[2]);
                ffma2(acc[p][3], aa, bb[3]);
            }
        }
    }

    const int cbase = blockIdx.y * 64 + tx * 4;
#pragma unroll
    for (int p = 0; p < 4; p++) {
        float2 c0 = unpack2(acc[p][0]);
        float2 c1 = unpack2(acc[p][1]);
        float2 c2 = unpack2(acc[p][2]);
        float2 c3 = unpack2(acc[p][3]);
        int row = r0 + ty * 8 + 2 * p;
        if (row < N_NODES) {
            *(float4*)&g_H[(size_t)row * 128 + cbase] = make_float4(c0.x, c1.x, c2.x, c3.x);
            *(float4*)&g_H[(size_t)(row + 1) * 128 + cbase] = make_float4(c0.y, c1.y, c2.y, c3.y);
        }
    }
}

// ---------------- vector reduction into global ----------------
__device__ __forceinline__ void red_v4(float* dst, float4 p) {
    asm volatile(
        "{\n\t"
        ".reg .u64 p64;\n\t"
        "cvta.to.global.u64 p64, %0;\n\t"
        "red.global.add.v4.f32 [p64], {%1, %2, %3, %4};\n\t"
        "}"
        :: "l"(dst), "f"(p.x), "f"(p.y), "f"(p.z), "f"(p.w)
        : "memory");
}
__device__ __forceinline__ float4 mul4(float4 h, float v) {
    return make_float4(h.x * v, h.y * v, h.z * v, h.w * v);
}

// ---------------- pass 1: AGG = A [h0|h1], deg1 = A 1  (warp per 4 edges) ----------------
__global__ __launch_bounds__(256) void spmm1_kernel(const int* __restrict__ ei,
                                                    const float* __restrict__ ea) {
    const int lane = threadIdx.x & 31;
    const int nwarps = gridDim.x * 8;
    const int w0 = (blockIdx.x * 256 + threadIdx.x) >> 5;
    const float4* H4 = (const float4*)g_H;
    const int4* R4 = (const int4*)ei;
    const int4* C4 = (const int4*)(ei + N_EDGES);
    const float4* V4 = (const float4*)ea;

    for (int b = w0; b < N_EDGES / 4; b += nwarps) {
        int4 r4 = __ldg(&R4[b]);
        int4 c4 = __ldg(&C4[b]);
        float4 v4 = __ldg(&V4[b]);
        float4 h0 = H4[(size_t)c4.x * 32 + lane];
        float4 h1 = H4[(size_t)c4.y * 32 + lane];
        float4 h2 = H4[(size_t)c4.z * 32 + lane];
        float4 h3 = H4[(size_t)c4.w * 32 + lane];
        red_v4(&g_AGG[(size_t)r4.x * 128 + lane * 4], mul4(h0, v4.x));
        red_v4(&g_AGG[(size_t)r4.y * 128 + lane * 4], mul4(h1, v4.y));
        red_v4(&g_AGG[(size_t)r4.z * 128 + lane * 4], mul4(h2, v4.z));
        red_v4(&g_AGG[(size_t)r4.w * 128 + lane * 4], mul4(h3, v4.w));
        if (lane == 0) {
            atomicAdd(&g_deg1[r4.x], v4.x);
            atomicAdd(&g_deg1[r4.y], v4.y);
            atomicAdd(&g_deg1[r4.z], v4.z);
            atomicAdd(&g_deg1[r4.w], v4.w);
        }
    }
}

// ---------------- pass 2: AGG2 = A (A h1), deg2 = A deg1  (half-warp per edge, 8/iter) ----
__global__ __launch_bounds__(256) void spmm2_kernel(const int* __restrict__ ei,
                                                    const float* __restrict__ ea) {
    const int lane = threadIdx.x & 31;
    const int half = lane >> 4;
    const int l = lane & 15;
    const int nwarps = gridDim.x * 8;
    const int w0 = (blockIdx.x * 256 + threadIdx.x) >> 5;
    const float4* T4 = (const float4*)g_AGG;
    const int4* R4 = (const int4*)ei;
    const int4* C4 = (const int4*)(ei + N_EDGES);
    const float4* V4 = (const float4*)ea;

    for (int it = w0; it < N_EDGES / 8; it += nwarps) {
        int b = it * 2 + half;
        int4 r4 = __ldg(&R4[b]);
        int4 c4 = __ldg(&C4[b]);
        float4 v4 = __ldg(&V4[b]);
        // cols 64..127 of AGG row c  (= (A h1)[c])
        float4 t0 = T4[(size_t)c4.x * 32 + 16 + l];
        float4 t1 = T4[(size_t)c4.y * 32 + 16 + l];
        float4 t2 = T4[(size_t)c4.z * 32 + 16 + l];
        float4 t3 = T4[(size_t)c4.w * 32 + 16 + l];
        red_v4(&g_AGG2[(size_t)r4.x * 64 + l * 4], mul4(t0, v4.x));
        red_v4(&g_AGG2[(size_t)r4.y * 64 + l * 4], mul4(t1, v4.y));
        red_v4(&g_AGG2[(size_t)r4.z * 64 + l * 4], mul4(t2, v4.z));
        red_v4(&g_AGG2[(size_t)r4.w * 64 + l * 4], mul4(t3, v4.w));
        if (l == 0) {
            float d0 = g_deg1[c4.x];
            float d1 = g_deg1[c4.y];
            float d2 = g_deg1[c4.z];
            float d3 = g_deg1[c4.w];
            atomicAdd(&g_deg2[r4.x], v4.x * d0);
            atomicAdd(&g_deg2[r4.y], v4.y * d1);
            atomicAdd(&g_deg2[r4.z], v4.z * d2);
            atomicAdd(&g_deg2[r4.w], v4.w * d3);
        }
    }
}

// ---------------- epilogue: both hops in one grid (warp per row) ----------------
__global__ __launch_bounds__(256) void epi_kernel(const float* __restrict__ b0,
                                                  const float* __restrict__ fc0,
                                                  const float* __restrict__ bf0,
                                                  const float* __restrict__ b1,
                                                  const float* __restrict__ fc1,
                                                  const float* __restrict__ bf1,
                                                  float* __restrict__ out) {
    const int w = (blockIdx.x * 256 + threadIdx.x) >> 5;
    const int lane = threadIdx.x & 31;
    if (w >= 2 * N_NODES) return;
    const int hop = (w >= N_NODES);
    const int node = hop ? (w - N_NODES) : w;

    const float* agg = hop ? g_AGG2 : g_AGG;
    const int stride = hop ? 64 : 128;
    const float d = hop ? g_deg2[node] : g_deg1[node];
    const float* b = hop ? b1 : b0;
    const float* fc = hop ? fc1 : fc0;
    const float* bf = hop ? bf1 : bf0;

    float2 acc = *(const float2*)&agg[(size_t)node * stride + 2 * lane];
    float2 y;
    if (d > 0.f) {
        float inv = 1.f / d;
        y.x = acc.x * inv;
        y.y = acc.y * inv;
    } else {
        y.x = 0.f;
        y.y = 0.f;
    }
    y.x += __ldg(&b[2 * lane]);
    y.y += __ldg(&b[2 * lane + 1]);

    float dot = y.x * __ldg(&fc[2 * lane]) + y.y * __ldg(&fc[2 * lane + 1]);
#pragma unroll
    for (int s = 16; s; s >>= 1) dot += __shfl_xor_sync(0xffffffffu, dot, s);
    float g = 1.f / (1.f + expf(-(dot + __ldg(&bf[0]))));

    float2 o;
    o.x = (y.x > 0.f) ? y.x : g * y.x;
    o.y = (y.y > 0.f) ? y.y : g * y.y;
    *(float2*)&out[(size_t)node * 128 + hop * 64 + 2 * lane] = o;
}

// ---------------- launch ----------------
extern "C" void kernel_launch(void* const* d_in, const int* in_sizes, int n_in,
                              void* d_out, int out_size) {
    const float* x   = (const float*)d_in[0];
    const int*   ei  = (const int*)d_in[1];
    const float* ea  = (const float*)d_in[2];
    const float* W0  = (const float*)d_in[3];
    const float* b0  = (const float*)d_in[4];
    const float* W1  = (const float*)d_in[5];
    const float* b1  = (const float*)d_in[6];
    const float* fc0 = (const float*)d_in[7];
    const float* bf0 = (const float*)d_in[8];
    const float* fc1 = (const float*)d_in[9];
    const float* bf1 = (const float*)d_in[10];
    float* out = (float*)d_out;

    zero_kernel<<<2048, 256>>>();

    dim3 ggrid((N_NODES + 127) / 128, 2);
    gemm_kernel<<<ggrid, 256>>>(x, W0, W1);

    spmm1_kernel<<<2048, 256>>>(ei, ea);
    spmm2_kernel<<<2048, 256>>>(ei, ea);

    epi_kernel<<<(2 * N_NODES * 32 + 255) / 256, 256>>>(b0, fc0, bf0, b1, fc1, bf1, out);
}

// round 3
// speedup vs baseline: 1.5434x; 1.1773x over previous
#include <cuda_runtime.h>
#include <math.h>

#define N_NODES 100000
#define N_EDGES 1000000
#define SCAN_BLK 98               // ceil(100000 / 1024)

// ---------------- scratch (static device globals; no allocation) ----------------
__device__ float g_H[(size_t)N_NODES * 128];     // [N][128] : x@W0 | x@W1
__device__ float g_AGG[(size_t)N_NODES * 128];   // [N][128] : A h0  | A h1
__device__ float g_AGG2[(size_t)N_NODES * 64];   // [N][64]  : A (A h1)
__device__ float g_deg1[N_NODES];                // A 1
__device__ float g_deg2[N_NODES];                // A deg1

// CSR build scratch
__device__ int   g_cnt[N_NODES];                 // histogram / then unused
__device__ int   g_cur[N_NODES];                 // scatter cursors
__device__ int   g_ptr[N_NODES + 1];             // row_ptr (exclusive)
__device__ int   g_blk[128];                     // block sums for scan
__device__ int   g_pcol[N_EDGES];                // CSR col
__device__ float g_pval[N_EDGES];                // CSR val

// ---------------- zero counters ----------------
__global__ void zero_kernel() {
    const int stride = gridDim.x * blockDim.x;
    for (int i = blockIdx.x * blockDim.x + threadIdx.x; i < N_NODES; i += stride) {
        g_cnt[i] = 0;
        g_cur[i] = 0;
    }
}

// ---------------- histogram of rows ----------------
__global__ void hist_kernel(const int* __restrict__ ei) {
    const int stride = gridDim.x * blockDim.x;
    const int4* R4 = (const int4*)ei;
    for (int i = blockIdx.x * blockDim.x + threadIdx.x; i < N_EDGES / 4; i += stride) {
        int4 r = __ldg(&R4[i]);
        atomicAdd(&g_cnt[r.x], 1);
        atomicAdd(&g_cnt[r.y], 1);
        atomicAdd(&g_cnt[r.z], 1);
        atomicAdd(&g_cnt[r.w], 1);
    }
}

// ---------------- scan stage 1: per-block exclusive scan (1024 items/block) ----------------
__global__ __launch_bounds__(256) void scan1_kernel() {
    __shared__ int sh[256];
    const int t = threadIdx.x;
    const int base = blockIdx.x * 1024 + t * 4;
    int c0 = (base + 0 < N_NODES) ? g_cnt[base + 0] : 0;
    int c1 = (base + 1 < N_NODES) ? g_cnt[base + 1] : 0;
    int c2 = (base + 2 < N_NODES) ? g_cnt[base + 2] : 0;
    int c3 = (base + 3 < N_NODES) ? g_cnt[base + 3] : 0;
    int tsum = c0 + c1 + c2 + c3;
    sh[t] = tsum;
    __syncthreads();
    for (int off = 1; off < 256; off <<= 1) {
        int v = (t >= off) ? sh[t - off] : 0;
        __syncthreads();
        if (t >= off) sh[t] += v;
        __syncthreads();
    }
    int excl = (t > 0) ? sh[t - 1] : 0;
    if (t == 255) g_blk[blockIdx.x] = sh[255];
    if (base + 0 < N_NODES) g_ptr[base + 0] = excl;
    if (base + 1 < N_NODES) g_ptr[base + 1] = excl + c0;
    if (base + 2 < N_NODES) g_ptr[base + 2] = excl + c0 + c1;
    if (base + 3 < N_NODES) g_ptr[base + 3] = excl + c0 + c1 + c2;
}

// ---------------- scan stage 2: scan block sums (single block) ----------------
__global__ __launch_bounds__(128) void scan2_kernel() {
    __shared__ int sh[128];
    const int t = threadIdx.x;
    int v = (t < SCAN_BLK) ? g_blk[t] : 0;
    sh[t] = v;
    __syncthreads();
    for (int off = 1; off < 128; off <<= 1) {
        int u = (t >= off) ? sh[t - off] : 0;
        __syncthreads();
        if (t >= off) sh[t] += u;
        __syncthreads();
    }
    if (t < SCAN_BLK) g_blk[t] = (t > 0) ? sh[t - 1] : 0;   // exclusive
}

// ---------------- scan stage 3: add block offsets ----------------
__global__ void scan3_kernel() {
    const int stride = gridDim.x * blockDim.x;
    for (int i = blockIdx.x * blockDim.x + threadIdx.x; i < N_NODES; i += stride)
        g_ptr[i] += g_blk[i >> 10];
    if (blockIdx.x == 0 && threadIdx.x == 0) g_ptr[N_NODES] = N_EDGES;
}

// ---------------- scatter edges into CSR order ----------------
__global__ void scatter_kernel(const int* __restrict__ ei, const float* __restrict__ ea) {
    const int e = blockIdx.x * blockDim.x + threadIdx.x;
    if (e >= N_EDGES) return;
    int r = __ldg(&ei[e]);
    int c = __ldg(&ei[N_EDGES + e]);
    float v = __ldg(&ea[e]);
    int pos = g_ptr[r] + atomicAdd(&g_cur[r], 1);
    g_pcol[pos] = c;
    g_pval[pos] = v;
}

// ---------------- packed f32x2 helpers ----------------
__device__ __forceinline__ unsigned long long pack2(float a, float b) {
    unsigned long long r;
    asm("mov.b64 %0, {%1, %2};" : "=l"(r) : "f"(a), "f"(b));
    return r;
}
__device__ __forceinline__ void ffma2(unsigned long long& d, unsigned long long a,
                                      unsigned long long b) {
    asm("fma.rn.f32x2 %0, %1, %2, %0;" : "+l"(d) : "l"(a), "l"(b));
}
__device__ __forceinline__ float2 unpack2(unsigned long long v) {
    float2 f;
    asm("mov.b64 {%0, %1}, %2;" : "=f"(f.x), "=f"(f.y) : "l"(v));
    return f;
}

// ---------------- GEMM: H[:,0:64] = x@W0, H[:,64:128] = x@W1 ----------------
__global__ __launch_bounds__(256) void gemm_kernel(const float* __restrict__ x,
                                                   const float* __restrict__ W0,
                                                   const float* __restrict__ W1) {
    __shared__ float Ws[128 * 64];
    __shared__ unsigned long long Xs2[64 * 17];

    const float* W = blockIdx.y ? W1 : W0;
    const int tid = threadIdx.x;
    for (int i = tid; i < 128 * 64 / 4; i += 256)
        ((float4*)Ws)[i] = ((const float4*)W)[i];

    const int r0 = blockIdx.x * 128;
    const int tx = tid & 15;
    const int ty = tid >> 4;

    unsigned long long acc[4][4];
#pragma unroll
    for (int p = 0; p < 4; p++)
#pragma unroll
        for (int c = 0; c < 4; c++) acc[p][c] = 0ull;

    float* Xf = (float*)Xs2;

    for (int kk = 0; kk < 128; kk += 16) {
        __syncthreads();
#pragma unroll
        for (int i = 0; i < 2; i++) {
            int idx = tid + i * 256;
            int rr = idx >> 2;
            int kq = idx & 3;
            int row = r0 + rr;
            float4 v = (row < N_NODES)
                           ? *(const float4*)&x[(size_t)row * 128 + kk + kq * 4]
                           : make_float4(0.f, 0.f, 0.f, 0.f);
            int p = rr >> 1, half = rr & 1;
            float* dst = &Xf[((p * 17) + kq * 4) * 2 + half];
            dst[0] = v.x; dst[2] = v.y; dst[4] = v.z; dst[6] = v.w;
        }
        __syncthreads();
#pragma unroll
        for (int k = 0; k < 16; k++) {
            float4 b = *(const float4*)&Ws[(kk + k) * 64 + tx * 4];
            unsigned long long bb[4];
            bb[0] = pack2(b.x, b.x);
            bb[1] = pack2(b.y, b.y);
            bb[2] = pack2(b.z, b.z);
            bb[3] = pack2(b.w, b.w);
#pragma unroll
            for (int p = 0; p < 4; p++) {
                unsigned long long aa = Xs2[(ty * 4 + p) * 17 + k];
                ffma2(acc[p][0], aa, bb[0]);
                ffma2(acc[p][1], aa, bb[1]);
                ffma2(acc[p][2], aa, bb[2]);
                ffma2(acc[p][3], aa, bb[3]);
            }
        }
    }

    const int cbase = blockIdx.y * 64 + tx * 4;
#pragma unroll
    for (int p = 0; p < 4; p++) {
        float2 c0 = unpack2(acc[p][0]);
        float2 c1 = unpack2(acc[p][1]);
        float2 c2 = unpack2(acc[p][2]);
        float2 c3 = unpack2(acc[p][3]);
        int row = r0 + ty * 8 + 2 * p;
        if (row < N_NODES) {
            *(float4*)&g_H[(size_t)row * 128 + cbase] = make_float4(c0.x, c1.x, c2.x, c3.x);
            *(float4*)&g_H[(size_t)(row + 1) * 128 + cbase] = make_float4(c0.y, c1.y, c2.y, c3.y);
        }
    }
}

// ---------------- pass 1: AGG[r] = sum_e val*H[col], deg1 (warp per row) ----------------
__global__ __launch_bounds__(256) void spmm1_csr(void) {
    const int w = (blockIdx.x * 256 + threadIdx.x) >> 5;
    const int lane = threadIdx.x & 31;
    if (w >= N_NODES) return;
    const int s = g_ptr[w];
    const int e = g_ptr[w + 1];
    const float4* H4 = (const float4*)g_H;

    float4 acc = make_float4(0.f, 0.f, 0.f, 0.f);
    float deg = 0.f;
    int i = s;
    for (; i + 2 <= e; i += 2) {
        int c0 = g_pcol[i];
        int c1 = g_pcol[i + 1];
        float v0 = g_pval[i];
        float v1 = g_pval[i + 1];
        float4 h0 = H4[(size_t)c0 * 32 + lane];
        float4 h1 = H4[(size_t)c1 * 32 + lane];
        acc.x += v0 * h0.x + v1 * h1.x;
        acc.y += v0 * h0.y + v1 * h1.y;
        acc.z += v0 * h0.z + v1 * h1.z;
        acc.w += v0 * h0.w + v1 * h1.w;
        deg += v0 + v1;
    }
    if (i < e) {
        int c0 = g_pcol[i];
        float v0 = g_pval[i];
        float4 h0 = H4[(size_t)c0 * 32 + lane];
        acc.x += v0 * h0.x;
        acc.y += v0 * h0.y;
        acc.z += v0 * h0.z;
        acc.w += v0 * h0.w;
        deg += v0;
    }
    ((float4*)g_AGG)[(size_t)w * 32 + lane] = acc;
    if (lane == 0) g_deg1[w] = deg;
}

// ---------------- pass 2: AGG2[r] = sum_e val*(A h1)[col], deg2 (warp per row) --------
__global__ __launch_bounds__(256) void spmm2_csr(void) {
    const int w = (blockIdx.x * 256 + threadIdx.x) >> 5;
    const int lane = threadIdx.x & 31;
    if (w >= N_NODES) return;
    const int s = g_ptr[w];
    const int e = g_ptr[w + 1];
    // T[c][j] = g_AGG[c*128 + 64 + j], j in 0..63 ; float2 per lane
    const float2* T2 = (const float2*)(g_AGG);

    float2 acc = make_float2(0.f, 0.f);
    float deg = 0.f;
    int i = s;
    for (; i + 2 <= e; i += 2) {
        int c0 = g_pcol[i];
        int c1 = g_pcol[i + 1];
        float v0 = g_pval[i];
        float v1 = g_pval[i + 1];
        float2 t0 = T2[(size_t)c0 * 64 + 32 + lane];
        float2 t1 = T2[(size_t)c1 * 64 + 32 + lane];
        float d0 = g_deg1[c0];
        float d1 = g_deg1[c1];
        acc.x += v0 * t0.x + v1 * t1.x;
        acc.y += v0 * t0.y + v1 * t1.y;
        deg += v0 * d0 + v1 * d1;
    }
    if (i < e) {
        int c0 = g_pcol[i];
        float v0 = g_pval[i];
        float2 t0 = T2[(size_t)c0 * 64 + 32 + lane];
        acc.x += v0 * t0.x;
        acc.y += v0 * t0.y;
        deg += v0 * g_deg1[c0];
    }
    ((float2*)g_AGG2)[(size_t)w * 32 + lane] = acc;
    if (lane == 0) g_deg2[w] = deg;
}

// ---------------- epilogue: both hops in one grid (warp per row) ----------------
__global__ __launch_bounds__(256) void epi_kernel(const float* __restrict__ b0,
                                                  const float* __restrict__ fc0,
                                                  const float* __restrict__ bf0,
                                                  const float* __restrict__ b1,
                                                  const float* __restrict__ fc1,
                                                  const float* __restrict__ bf1,
                                                  float* __restrict__ out) {
    const int w = (blockIdx.x * 256 + threadIdx.x) >> 5;
    const int lane = threadIdx.x & 31;
    if (w >= 2 * N_NODES) return;
    const int hop = (w >= N_NODES);
    const int node = hop ? (w - N_NODES) : w;

    const float* agg = hop ? g_AGG2 : g_AGG;
    const int stride = hop ? 64 : 128;
    const float d = hop ? g_deg2[node] : g_deg1[node];
    const float* b = hop ? b1 : b0;
    const float* fc = hop ? fc1 : fc0;
    const float* bf = hop ? bf1 : bf0;

    float2 acc = *(const float2*)&agg[(size_t)node * stride + 2 * lane];
    float2 y;
    if (d > 0.f) {
        float inv = 1.f / d;
        y.x = acc.x * inv;
        y.y = acc.y * inv;
    } else {
        y.x = 0.f;
        y.y = 0.f;
    }
    y.x += __ldg(&b[2 * lane]);
    y.y += __ldg(&b[2 * lane + 1]);

    float dot = y.x * __ldg(&fc[2 * lane]) + y.y * __ldg(&fc[2 * lane + 1]);
#pragma unroll
    for (int s = 16; s; s >>= 1) dot += __shfl_xor_sync(0xffffffffu, dot, s);
    float g = 1.f / (1.f + expf(-(dot + __ldg(&bf[0]))));

    float2 o;
    o.x = (y.x > 0.f) ? y.x : g * y.x;
    o.y = (y.y > 0.f) ? y.y : g * y.y;
    *(float2*)&out[(size_t)node * 128 + hop * 64 + 2 * lane] = o;
}

// ---------------- launch ----------------
extern "C" void kernel_launch(void* const* d_in, const int* in_sizes, int n_in,
                              void* d_out, int out_size) {
    const float* x   = (const float*)d_in[0];
    const int*   ei  = (const int*)d_in[1];
    const float* ea  = (const float*)d_in[2];
    const float* W0  = (const float*)d_in[3];
    const float* b0  = (const float*)d_in[4];
    const float* W1  = (const float*)d_in[5];
    const float* b1  = (const float*)d_in[6];
    const float* fc0 = (const float*)d_in[7];
    const float* bf0 = (const float*)d_in[8];
    const float* fc1 = (const float*)d_in[9];
    const float* bf1 = (const float*)d_in[10];
    float* out = (float*)d_out;

    // CSR build
    zero_kernel<<<512, 256>>>();
    hist_kernel<<<512, 256>>>(ei);
    scan1_kernel<<<SCAN_BLK, 256>>>();
    scan2_kernel<<<1, 128>>>();
    scan3_kernel<<<512, 256>>>();
    scatter_kernel<<<(N_EDGES + 255) / 256, 256>>>(ei, ea);

    // dense
    dim3 ggrid((N_NODES + 127) / 128, 2);
    gemm_kernel<<<ggrid, 256>>>(x, W0, W1);

    // aggregation
    spmm1_csr<<<(N_NODES * 32 + 255) / 256, 256>>>();
    spmm2_csr<<<(N_NODES * 32 + 255) / 256, 256>>>();

    // epilogue
    epi_kernel<<<(2 * N_NODES * 32 + 255) / 256, 256>>>(b0, fc0, bf0, b1, fc1, bf1, out);
}